// round 13
// baseline (speedup 1.0000x reference)
#include <cuda_runtime.h>
#include <cuda_bf16.h>
#include <cstdint>
#include <cstddef>

#define NN 512     // graph nodes
#define BB 8       // batch
#define TT 128     // time steps
#define FF 64      // features
#define NBLK 128   // persistent grid (8 m-tiles x 8 batches x 2 f-halves)
#define GRPSZ 8    // blocks per dependency group (same (b, f-half))

// ---------------- device scratch (static; no allocations) ----------------
__device__ float g_LpI[NN*NN];
__device__ float g_X [NN*NN];
__device__ float g_X2[NN*NN];
__device__ float g_R [NN*NN];
__device__ float g_P0[NN*NN];    // k-split partial 0
__device__ float g_P1[NN*NN];    // k-split partial 1
__device__ float g_d   [NN];
__device__ float g_dinv[NN];
__device__ float g_sfix[1];
__device__ __align__(16) __nv_bfloat16 g_Mhi[NN*NN];
__device__ __align__(16) __nv_bfloat16 g_Mlo[NN*NN];
// Z scratch: [parity][b][f][k] bf16, double-buffered across steps
__device__ __align__(16) __nv_bfloat16 g_zhi[2][BB][FF][NN];
__device__ __align__(16) __nv_bfloat16 g_zlo[2][BB][FF][NN];
// 16 independent group barriers (one per (b, f-half)); padded lines
__device__ __align__(128) unsigned g_gcount[16][32];
__device__ __align__(128) unsigned g_ggen  [16][32];

// ---------------- helpers ----------------
__device__ __forceinline__ uint32_t smem_u32(const void* p) {
    uint32_t a;
    asm("{ .reg .u64 t; cvta.to.shared.u64 t, %1; cvt.u32.u64 %0, t; }" : "=r"(a) : "l"(p));
    return a;
}
__device__ __forceinline__ void cp_async16(uint32_t dst, const void* src) {
    asm volatile("cp.async.cg.shared.global [%0], [%1], 16;" :: "r"(dst), "l"(src) : "memory");
}
__device__ __forceinline__ void cp_commit() {
    asm volatile("cp.async.commit_group;" ::: "memory");
}
__device__ __forceinline__ void cp_wait(int n) {
    switch (n) {
    case 0: asm volatile("cp.async.wait_group 0;" ::: "memory"); break;
    case 1: asm volatile("cp.async.wait_group 1;" ::: "memory"); break;
    case 2: asm volatile("cp.async.wait_group 2;" ::: "memory"); break;
    default: asm volatile("cp.async.wait_group 3;" ::: "memory"); break;
    }
}
__device__ __forceinline__ void ldsm4(uint32_t* r, uint32_t addr) {
    asm volatile("ldmatrix.sync.aligned.m8n8.x4.shared.b16 {%0,%1,%2,%3}, [%4];"
                 : "=r"(r[0]), "=r"(r[1]), "=r"(r[2]), "=r"(r[3]) : "r"(addr));
}
__device__ __forceinline__ void mma_bf16(float* c, const uint32_t* a, uint32_t b0, uint32_t b1) {
    asm volatile("mma.sync.aligned.m16n8k16.row.col.f32.bf16.bf16.f32 "
                 "{%0,%1,%2,%3}, {%4,%5,%6,%7}, {%8,%9}, {%0,%1,%2,%3};"
                 : "+f"(c[0]), "+f"(c[1]), "+f"(c[2]), "+f"(c[3])
                 : "r"(a[0]), "r"(a[1]), "r"(a[2]), "r"(a[3]), "r"(b0), "r"(b1));
}
__device__ __forceinline__ void split1(float v, __nv_bfloat16& hi, __nv_bfloat16& lo) {
    hi = __float2bfloat16_rn(v);
    lo = __float2bfloat16_rn(v - __bfloat162float(hi));
}
__device__ __forceinline__ unsigned ld_acq(const unsigned* p) {
    unsigned v;
    asm volatile("ld.global.acquire.gpu.u32 %0, [%1];" : "=r"(v) : "l"(p));
    return v;
}
// full sub-group barrier (prologue use): 8 blocks sharing (b, f-half)
__device__ __forceinline__ void group_sync(int g) {
    __syncthreads();
    if (threadIdx.x == 0) {
        unsigned* cnt = &g_gcount[g][0];
        unsigned* gen = &g_ggen[g][0];
        unsigned cur = ld_acq(gen);
        __threadfence();
        unsigned prev = atomicAdd(cnt, 1);
        if (prev == GRPSZ - 1) {
            atomicExch(cnt, 0);
            __threadfence();
            atomicAdd(gen, 1);
        } else {
            while (ld_acq(gen) == cur) { }
        }
    }
    __syncthreads();
}

// ---------------- setup kernels (SIMT, run once) ----------------
__global__ void rowsum_kernel(const float* __restrict__ A) {
    int row = blockIdx.x, tid = threadIdx.x;
    const float* ar = A + (size_t)row * NN;
    float s = ar[tid] + ar[tid + 128] + ar[tid + 256] + ar[tid + 384];
    __shared__ float red[128];
    red[tid] = s; __syncthreads();
    for (int off = 64; off > 0; off >>= 1) { if (tid < off) red[tid] += red[tid + off]; __syncthreads(); }
    if (tid == 0) { float d = red[0] + 1.0f; g_d[row] = d; g_dinv[row] = 1.0f / d; }
}

__global__ void build_kernel(const float* __restrict__ A) {
    int i = blockIdx.x, j = threadIdx.x;
    size_t idx = (size_t)i * NN + j;
    g_LpI[idx] = (i == j ? g_d[i] : 0.0f) - A[idx];
}

// X1 = 2*X0 - X0(L+I)X0 with X0 = D^-1 (diagonal) -> elementwise, replaces 2 GEMMs.
// Matches the GEMM path bit-for-bit (each inner sum has exactly one nonzero term).
__global__ void build_x1_kernel() {
    int i = blockIdx.x, j = threadIdx.x;
    size_t idx = (size_t)i * NN + j;
    float r = __fmul_rn(g_LpI[idx], g_dinv[j]);
    float s = __fmul_rn(g_dinv[i], r);
    g_X[idx] = (i == j ? 2.0f * g_dinv[i] : 0.0f) - s;
}

__global__ void trace_kernel() {
    __shared__ double red[256];
    int tid = threadIdx.x;
    red[tid] = (double)g_R[(size_t)tid * (NN + 1)] + (double)g_R[(size_t)(tid + 256) * (NN + 1)];
    __syncthreads();
    for (int off = 128; off > 0; off >>= 1) { if (tid < off) red[tid] += red[tid + off]; __syncthreads(); }
    if (tid == 0) g_sfix[0] = (float)(1.0 / (1.0 - red[0]));
}

// k-split partial GEMM: P[z] = A[:, kz:kz+256] @ B[kz:kz+256, :]
__global__ void __launch_bounds__(256) gemm_part(const float* __restrict__ Am,
                                                 const float* __restrict__ Bm,
                                                 float* __restrict__ P0,
                                                 float* __restrict__ P1) {
    __shared__ float As[32][68];
    __shared__ float Bs[32][36];
    float* Cm = blockIdx.z ? P1 : P0;
    int kbase = blockIdx.z << 8;
    int tid = threadIdx.x;
    int tm = tid >> 4, tn = tid & 15;
    int m0 = blockIdx.y * 64, n0 = blockIdx.x * 32;
    float acc[4][2] = {};
    int lm = tid >> 3, lk4 = (tid & 7) << 2;
    int bk = tid >> 3, bn = (tid & 7) << 2;
    for (int k0 = kbase; k0 < kbase + 256; k0 += 32) {
        #pragma unroll
        for (int r = 0; r < 2; r++) {
            int m = lm + 32 * r;
            float4 v = *(const float4*)(Am + (size_t)(m0 + m) * NN + k0 + lk4);
            As[lk4 + 0][m] = v.x; As[lk4 + 1][m] = v.y; As[lk4 + 2][m] = v.z; As[lk4 + 3][m] = v.w;
        }
        *(float4*)&Bs[bk][bn] = *(const float4*)(Bm + (size_t)(k0 + bk) * NN + n0 + bn);
        __syncthreads();
        #pragma unroll
        for (int k = 0; k < 32; k++) {
            float4 a = *(const float4*)&As[k][tm << 2];
            float2 b = *(const float2*)&Bs[k][tn << 1];
            acc[0][0] += a.x * b.x; acc[0][1] += a.x * b.y;
            acc[1][0] += a.y * b.x; acc[1][1] += a.y * b.y;
            acc[2][0] += a.z * b.x; acc[2][1] += a.z * b.y;
            acc[3][0] += a.w * b.x; acc[3][1] += a.w * b.y;
        }
        __syncthreads();
    }
    int mbase = m0 + (tm << 2), nbase = n0 + (tn << 1);
    #pragma unroll
    for (int i = 0; i < 4; i++)
        #pragma unroll
        for (int j = 0; j < 2; j++)
            Cm[(size_t)(mbase + i) * NN + nbase + j] = acc[i][j];
}

// combine partials + MODE epilogue. 64 blocks x 256 thr x 4 float4 (MLP 8).
// MODE 0: C = S;  1: C = 2E - S;  2: C = I - S;  3: C = E + sfix*S
template<int MODE>
__global__ void combine(const float* __restrict__ P0, const float* __restrict__ P1,
                        const float* __restrict__ Em, float* __restrict__ Cm) {
    int base = blockIdx.x * 256 + threadIdx.x;   // 16384 threads
    #pragma unroll
    for (int j = 0; j < 4; j++) {
        size_t e = ((size_t)(base + j * 16384)) << 2;
        float4 a = *(const float4*)(P0 + e);
        float4 b = *(const float4*)(P1 + e);
        float4 s = make_float4(a.x + b.x, a.y + b.y, a.z + b.z, a.w + b.w);
        float4 c;
        if (MODE == 0) {
            c = s;
        } else if (MODE == 1) {
            float4 ev = *(const float4*)(Em + e);
            c = make_float4(2.f * ev.x - s.x, 2.f * ev.y - s.y, 2.f * ev.z - s.z, 2.f * ev.w - s.w);
        } else if (MODE == 2) {
            int m = (int)(e >> 9), n = (int)(e & 511);
            c.x = (m == n     ? 1.f : 0.f) - s.x;
            c.y = (m == n + 1 ? 1.f : 0.f) - s.y;
            c.z = (m == n + 2 ? 1.f : 0.f) - s.z;
            c.w = (m == n + 3 ? 1.f : 0.f) - s.w;
        } else {
            float sf = g_sfix[0];
            float4 ev = *(const float4*)(Em + e);
            c = make_float4(ev.x + sf * s.x, ev.y + sf * s.y, ev.z + sf * s.z, ev.w + sf * s.w);
        }
        *(float4*)(Cm + e) = c;
    }
}

__global__ void split_kernel(const float* __restrict__ M) {
    int i = blockIdx.x, j = threadIdx.x;
    size_t idx = (size_t)i * NN + j;
    float v = M[idx];
    __nv_bfloat16 h = __float2bfloat16_rn(v);
    g_Mhi[idx] = h;
    g_Mlo[idx] = __float2bfloat16_rn(v - __bfloat162float(h));
}

// ---------------- persistent warp-mma step kernel (916-run version, verbatim) --
// Block r: mi = r>>4 (64-row M tile), ci = r&15 -> b = ci>>1, f0 = (ci&1)*32.
// Dependency group = ci (16 groups of 8 blocks); y tile [64x32] lives in mma
// accumulators across all 128 steps.
// smem: Mhi(64x512) | Mlo | Zhi(32x512) | Zlo, rows padded to 1040B.
#define ASTRIDE  1040
#define MHI_OFF  0
#define MLO_OFF  66560
#define ZHI_OFF  133120
#define ZLO_OFF  166400
#define SM_TOTAL 199680

__global__ void __launch_bounds__(256, 1) step_persist(const float* __restrict__ xs,
                                                       float* __restrict__ out) {
    extern __shared__ char smem[];
    uint32_t sb = smem_u32(smem);
    int tid = threadIdx.x, lane = tid & 31, w = tid >> 5;
    int bx = blockIdx.x;
    int m0 = (bx >> 4) << 6;            // 0..448
    int ci = bx & 15;                   // dependency group id
    int b  = ci >> 1;
    int f0 = (ci & 1) << 5;             // 0 or 32
    unsigned* cnt = &g_gcount[ci][0];
    unsigned* gen = &g_ggen[ci][0];

    int wm = (w & 3) << 4;              // warp m offset within 64
    int wn = (w >> 2) << 4;             // warp f offset within 32

    // ldmatrix lane addresses
    uint32_t aAddr = sb + MHI_OFF + (uint32_t)(wm + (lane & 15)) * ASTRIDE + (((lane >> 4) << 3) << 1);
    uint32_t bAddr = sb + ZHI_OFF + (uint32_t)(wn + ((lane >> 4) << 3) + (lane & 7)) * ASTRIDE
                     + ((((lane >> 3) & 1) << 3) << 1);

    // --- prologue: load M slice into smem (once) ---
    {
        const char* mh = (const char*)(g_Mhi + (size_t)m0 * NN);
        const char* ml = (const char*)(g_Mlo + (size_t)m0 * NN);
        for (int i = tid; i < 64 * 64; i += 256) {
            int r = i >> 6, c = (i & 63) << 4;
            *(uint4*)(smem + MHI_OFF + r * ASTRIDE + c) = *(const uint4*)(mh + r * 1024 + c);
            *(uint4*)(smem + MLO_OFF + r * ASTRIDE + c) = *(const uint4*)(ml + r * 1024 + c);
        }
    }
    // --- prologue: Z0 = x_0 over owned tile -> scratch parity 0 ---
    for (int idx = tid; idx < 64 * 32; idx += 256) {
        int m = idx >> 5, f = idx & 31;
        int gm = m0 + m, gf = f0 + f;
        float v = xs[((size_t)(b * TT) * NN + gm) * FF + gf];
        __nv_bfloat16 h, l; split1(v, h, l);
        g_zhi[0][b][gf][gm] = h;
        g_zlo[0][b][gf][gm] = l;
    }
    group_sync(ci);

    float yacc[2][4] = {};   // y fragments (m16 x n16 per warp), persist across steps

    int r0 = lane >> 2, cc = (lane & 3) << 1;
    int mA = m0 + wm + r0;
    int fj0 = f0 + wn + cc;              // j=0 feature index; j=1 is fj0+8

    for (int t = 0; t < TT; t++) {
        int par = t & 1;
        const char* zh = (const char*)&g_zhi[par][b][f0][0];
        const char* zl = (const char*)&g_zlo[par][b][f0][0];

        // --- prefetch x_{t+1} (consumed in epilogue; latency hidden under mma) ---
        float2 xp00, xp01, xp10, xp11;
        bool notlast = (t < TT - 1);
        if (notlast) {
            const float* xp = xs + ((size_t)(b * TT + t + 1) * NN) * FF;
            xp00 = *(const float2*)(xp + (size_t)mA * FF + fj0);
            xp01 = *(const float2*)(xp + (size_t)(mA + 8) * FF + fj0);
            xp10 = *(const float2*)(xp + (size_t)mA * FF + fj0 + 8);
            xp11 = *(const float2*)(xp + (size_t)(mA + 8) * FF + fj0 + 8);
        }

        // --- issue Z_t in 4 k-quarters (cp.async, L1-bypassed) ---
        #pragma unroll
        for (int q = 0; q < 4; q++) {
            #pragma unroll
            for (int i = 0; i < 4; i++) {
                int idx = tid + (i << 8);
                int op = idx >> 9;
                int rem = idx & 511;
                int r = rem >> 4, c = rem & 15;
                uint32_t off = (uint32_t)r * ASTRIDE + (q << 8) + (c << 4);
                uint32_t goff = (uint32_t)r * 1024 + (q << 8) + (c << 4);
                if (op == 0) cp_async16(sb + ZHI_OFF + off, zh + goff);
                else         cp_async16(sb + ZLO_OFF + off, zl + goff);
            }
            cp_commit();
        }

        // --- mma per quarter, overlapped with remaining quarters' loads ---
        #pragma unroll
        for (int q = 0; q < 4; q++) {
            cp_wait(3 - q);
            __syncthreads();
            #pragma unroll 4
            for (int kk = 0; kk < 128; kk += 16) {
                int k0 = (q << 7) + kk;
                uint32_t ah[4], al[4], bh[4], bl[4];
                uint32_t ka = aAddr + (k0 << 1), kb = bAddr + (k0 << 1);
                ldsm4(ah, ka);
                ldsm4(al, ka + (MLO_OFF - MHI_OFF));
                ldsm4(bh, kb);
                ldsm4(bl, kb + (ZLO_OFF - ZHI_OFF));
                mma_bf16(yacc[0], ah, bh[0], bh[1]);
                mma_bf16(yacc[1], ah, bh[2], bh[3]);
                mma_bf16(yacc[0], ah, bl[0], bl[1]);
                mma_bf16(yacc[1], ah, bl[2], bl[3]);
                mma_bf16(yacc[0], al, bh[0], bh[1]);
                mma_bf16(yacc[1], al, bh[2], bh[3]);
            }
        }

        // --- epilogue: Z_{t+1} first (peers need it), then barrier-arrive,
        //     then out stores (nobody reads out: overlap with peers' wait) ---
        if (notlast) {
            int pn = (t + 1) & 1;
            __nv_bfloat16* zhn = &g_zhi[pn][b][0][0];
            __nv_bfloat16* zln = &g_zlo[pn][b][0][0];
            __nv_bfloat16 h, l;
            split1(xp00.x - yacc[0][0], h, l); zhn[(size_t)fj0 * NN + mA] = h;           zln[(size_t)fj0 * NN + mA] = l;
            split1(xp00.y - yacc[0][1], h, l); zhn[(size_t)(fj0 + 1) * NN + mA] = h;     zln[(size_t)(fj0 + 1) * NN + mA] = l;
            split1(xp01.x - yacc[0][2], h, l); zhn[(size_t)fj0 * NN + mA + 8] = h;       zln[(size_t)fj0 * NN + mA + 8] = l;
            split1(xp01.y - yacc[0][3], h, l); zhn[(size_t)(fj0 + 1) * NN + mA + 8] = h; zln[(size_t)(fj0 + 1) * NN + mA + 8] = l;
            split1(xp10.x - yacc[1][0], h, l); zhn[(size_t)(fj0 + 8) * NN + mA] = h;     zln[(size_t)(fj0 + 8) * NN + mA] = l;
            split1(xp10.y - yacc[1][1], h, l); zhn[(size_t)(fj0 + 9) * NN + mA] = h;     zln[(size_t)(fj0 + 9) * NN + mA] = l;
            split1(xp11.x - yacc[1][2], h, l); zhn[(size_t)(fj0 + 8) * NN + mA + 8] = h; zln[(size_t)(fj0 + 8) * NN + mA + 8] = l;
            split1(xp11.y - yacc[1][3], h, l); zhn[(size_t)(fj0 + 9) * NN + mA + 8] = h; zln[(size_t)(fj0 + 9) * NN + mA + 8] = l;
        }
        __syncthreads();                  // all Z stores issued

        unsigned phase = 0; int amlast = 0;
        if (tid == 0 && notlast) {
            phase = ld_acq(gen);
            __threadfence();              // order CTA's Z stores before arrival
            unsigned prev = atomicAdd(cnt, 1);
            if (prev == GRPSZ - 1) {
                amlast = 1;
                atomicExch(cnt, 0);
                __threadfence();
                atomicAdd(gen, 1);
            }
        }

        // out stores overlap the barrier propagation
        {
            float* op = out + ((size_t)(b * TT + t) * NN) * FF;
            *(float2*)(op + (size_t)mA * FF + fj0)           = make_float2(yacc[0][0], yacc[0][1]);
            *(float2*)(op + (size_t)(mA + 8) * FF + fj0)     = make_float2(yacc[0][2], yacc[0][3]);
            *(float2*)(op + (size_t)mA * FF + fj0 + 8)       = make_float2(yacc[1][0], yacc[1][1]);
            *(float2*)(op + (size_t)(mA + 8) * FF + fj0 + 8) = make_float2(yacc[1][2], yacc[1][3]);
        }

        if (tid == 0 && notlast && !amlast) {
            while (ld_acq(gen) == phase) { }
        }
        __syncthreads();
    }
}

// ---------------- host launcher ----------------
extern "C" void kernel_launch(void* const* d_in, const int* in_sizes, int n_in,
                              void* d_out, int out_size) {
    const float* xs = (const float*)d_in[0];  // [B,T,N,F]
    const float* A  = (const float*)d_in[1];  // [1,N,N]
    float* out = (float*)d_out;               // [B,T,N,F]

    float *pLpI, *pX, *pX2, *pR, *pP0, *pP1;
    cudaGetSymbolAddress((void**)&pLpI, g_LpI);
    cudaGetSymbolAddress((void**)&pX,   g_X);
    cudaGetSymbolAddress((void**)&pX2,  g_X2);
    cudaGetSymbolAddress((void**)&pR,   g_R);
    cudaGetSymbolAddress((void**)&pP0,  g_P0);
    cudaGetSymbolAddress((void**)&pP1,  g_P1);

    cudaFuncSetAttribute(step_persist, cudaFuncAttributeMaxDynamicSharedMemorySize, SM_TOTAL);

    // 1) build (L+I); X1 computed analytically (replaces first NS GEMM pair)
    rowsum_kernel<<<NN, 128>>>(A);
    build_kernel<<<NN, 512>>>(A);
    build_x1_kernel<<<NN, 512>>>();

    dim3 gridp(NN / 32, NN / 64, 2);   // k-split x2 -> 256 blocks
    dim3 gridc(64);

    // 2) Newton-Schulz iterations 2..4 (NS4 total; NS3 failed at 1.1e-3 in R7)
    float* Xin = pX; float* Xout = pX2;
    for (int it = 0; it < 3; it++) {
        gemm_part<<<gridp, 256>>>(pLpI, Xin, pP0, pP1);
        combine<0><<<gridc, 256>>>(pP0, pP1, nullptr, pR);      // R = (L+I)@X
        gemm_part<<<gridp, 256>>>(Xin, pR, pP0, pP1);
        combine<1><<<gridc, 256>>>(pP0, pP1, Xin, Xout);        // Xout = 2X - X@R
        float* tmp = Xin; Xin = Xout; Xout = tmp;
    }

    // 3) rank-1 closed-form fix: R = I - X@(L+I); M = X + R@X / (1 - tr R)
    gemm_part<<<gridp, 256>>>(Xin, pLpI, pP0, pP1);
    combine<2><<<gridc, 256>>>(pP0, pP1, nullptr, pR);
    trace_kernel<<<1, 256>>>();
    gemm_part<<<gridp, 256>>>(pR, Xin, pP0, pP1);
    combine<3><<<gridc, 256>>>(pP0, pP1, Xin, Xout);

    // 4) split M into bf16 hi/lo
    split_kernel<<<NN, 512>>>(Xout);

    // 5) all 128 recurrence steps in ONE persistent tensor-core kernel
    step_persist<<<NBLK, 256, SM_TOTAL>>>(xs, out);
}

// round 15
// speedup vs baseline: 1.4669x; 1.4669x over previous
#include <cuda_runtime.h>
#include <cuda_bf16.h>
#include <cstdint>
#include <cstddef>

#define NN 512     // graph nodes
#define BB 8       // batch
#define TT 128     // time steps
#define FF 64      // features
#define NBLK 128   // persistent grid (8 m-tiles x 8 batches x 2 f-halves)
#define GRPSZ 8    // blocks per dependency group (same (b, f-half))

// ---------------- device scratch (static; no allocations) ----------------
__device__ float g_LpI[NN*NN];
__device__ float g_X [NN*NN];
__device__ float g_X2[NN*NN];
__device__ float g_R [NN*NN];
__device__ float g_P0[NN*NN];    // k-split partial 0
__device__ float g_P1[NN*NN];    // k-split partial 1
__device__ float g_d   [NN];
__device__ float g_dinv[NN];
__device__ float g_sfix[1];
__device__ __align__(16) __nv_bfloat16 g_Mhi[NN*NN];
__device__ __align__(16) __nv_bfloat16 g_Mlo[NN*NN];
// Z scratch: [parity][b][f][k] bf16, double-buffered across steps
__device__ __align__(16) __nv_bfloat16 g_zhi[2][BB][FF][NN];
__device__ __align__(16) __nv_bfloat16 g_zlo[2][BB][FF][NN];
// 16 independent group barriers (one per (b, f-half)); padded lines
__device__ __align__(128) unsigned g_gcount[16][32];
__device__ __align__(128) unsigned g_ggen  [16][32];

// ---------------- helpers ----------------
__device__ __forceinline__ uint32_t smem_u32(const void* p) {
    uint32_t a;
    asm("{ .reg .u64 t; cvta.to.shared.u64 t, %1; cvt.u32.u64 %0, t; }" : "=r"(a) : "l"(p));
    return a;
}
__device__ __forceinline__ void cp_async16(uint32_t dst, const void* src) {
    asm volatile("cp.async.cg.shared.global [%0], [%1], 16;" :: "r"(dst), "l"(src) : "memory");
}
__device__ __forceinline__ void cp_commit() {
    asm volatile("cp.async.commit_group;" ::: "memory");
}
__device__ __forceinline__ void cp_wait(int n) {
    switch (n) {
    case 0: asm volatile("cp.async.wait_group 0;" ::: "memory"); break;
    case 1: asm volatile("cp.async.wait_group 1;" ::: "memory"); break;
    case 2: asm volatile("cp.async.wait_group 2;" ::: "memory"); break;
    default: asm volatile("cp.async.wait_group 3;" ::: "memory"); break;
    }
}
__device__ __forceinline__ void ldsm4(uint32_t* r, uint32_t addr) {
    asm volatile("ldmatrix.sync.aligned.m8n8.x4.shared.b16 {%0,%1,%2,%3}, [%4];"
                 : "=r"(r[0]), "=r"(r[1]), "=r"(r[2]), "=r"(r[3]) : "r"(addr));
}
__device__ __forceinline__ void mma_bf16(float* c, const uint32_t* a, uint32_t b0, uint32_t b1) {
    asm volatile("mma.sync.aligned.m16n8k16.row.col.f32.bf16.bf16.f32 "
                 "{%0,%1,%2,%3}, {%4,%5,%6,%7}, {%8,%9}, {%0,%1,%2,%3};"
                 : "+f"(c[0]), "+f"(c[1]), "+f"(c[2]), "+f"(c[3])
                 : "r"(a[0]), "r"(a[1]), "r"(a[2]), "r"(a[3]), "r"(b0), "r"(b1));
}
__device__ __forceinline__ void split1(float v, __nv_bfloat16& hi, __nv_bfloat16& lo) {
    hi = __float2bfloat16_rn(v);
    lo = __float2bfloat16_rn(v - __bfloat162float(hi));
}
__device__ __forceinline__ unsigned ld_acq(const unsigned* p) {
    unsigned v;
    asm volatile("ld.global.acquire.gpu.u32 %0, [%1];" : "=r"(v) : "l"(p));
    return v;
}
// full sub-group barrier (prologue use): 8 blocks sharing (b, f-half)
__device__ __forceinline__ void group_sync(int g) {
    __syncthreads();
    if (threadIdx.x == 0) {
        unsigned* cnt = &g_gcount[g][0];
        unsigned* gen = &g_ggen[g][0];
        unsigned cur = ld_acq(gen);
        __threadfence();
        unsigned prev = atomicAdd(cnt, 1);
        if (prev == GRPSZ - 1) {
            atomicExch(cnt, 0);
            __threadfence();
            atomicAdd(gen, 1);
        } else {
            while (ld_acq(gen) == cur) { }
        }
    }
    __syncthreads();
}

// ---------------- setup kernels (SIMT, run once) ----------------
__global__ void rowsum_kernel(const float* __restrict__ A) {
    int row = blockIdx.x, tid = threadIdx.x;
    const float* ar = A + (size_t)row * NN;
    float s = ar[tid] + ar[tid + 128] + ar[tid + 256] + ar[tid + 384];
    __shared__ float red[128];
    red[tid] = s; __syncthreads();
    for (int off = 64; off > 0; off >>= 1) { if (tid < off) red[tid] += red[tid + off]; __syncthreads(); }
    if (tid == 0) { float d = red[0] + 1.0f; g_d[row] = d; g_dinv[row] = 1.0f / d; }
}

__global__ void build_kernel(const float* __restrict__ A) {
    int i = blockIdx.x, j = threadIdx.x;
    size_t idx = (size_t)i * NN + j;
    g_LpI[idx] = (i == j ? g_d[i] : 0.0f) - A[idx];
}

// X1 = 2*X0 - X0(L+I)X0 with X0 = D^-1 (diagonal) -> elementwise, replaces 2 GEMMs.
// Matches the GEMM path bit-for-bit (each inner sum has exactly one nonzero term).
__global__ void build_x1_kernel() {
    int i = blockIdx.x, j = threadIdx.x;
    size_t idx = (size_t)i * NN + j;
    float r = __fmul_rn(g_LpI[idx], g_dinv[j]);
    float s = __fmul_rn(g_dinv[i], r);
    g_X[idx] = (i == j ? 2.0f * g_dinv[i] : 0.0f) - s;
}

__global__ void trace_kernel() {
    __shared__ double red[256];
    int tid = threadIdx.x;
    red[tid] = (double)g_R[(size_t)tid * (NN + 1)] + (double)g_R[(size_t)(tid + 256) * (NN + 1)];
    __syncthreads();
    for (int off = 128; off > 0; off >>= 1) { if (tid < off) red[tid] += red[tid + off]; __syncthreads(); }
    if (tid == 0) g_sfix[0] = (float)(1.0 / (1.0 - red[0]));
}

// k-split partial GEMM: P[z] = A[:, kz:kz+256] @ B[kz:kz+256, :]
__global__ void __launch_bounds__(256) gemm_part(const float* __restrict__ Am,
                                                 const float* __restrict__ Bm,
                                                 float* __restrict__ P0,
                                                 float* __restrict__ P1) {
    __shared__ float As[32][68];
    __shared__ float Bs[32][36];
    float* Cm = blockIdx.z ? P1 : P0;
    int kbase = blockIdx.z << 8;
    int tid = threadIdx.x;
    int tm = tid >> 4, tn = tid & 15;
    int m0 = blockIdx.y * 64, n0 = blockIdx.x * 32;
    float acc[4][2] = {};
    int lm = tid >> 3, lk4 = (tid & 7) << 2;
    int bk = tid >> 3, bn = (tid & 7) << 2;
    for (int k0 = kbase; k0 < kbase + 256; k0 += 32) {
        #pragma unroll
        for (int r = 0; r < 2; r++) {
            int m = lm + 32 * r;
            float4 v = *(const float4*)(Am + (size_t)(m0 + m) * NN + k0 + lk4);
            As[lk4 + 0][m] = v.x; As[lk4 + 1][m] = v.y; As[lk4 + 2][m] = v.z; As[lk4 + 3][m] = v.w;
        }
        *(float4*)&Bs[bk][bn] = *(const float4*)(Bm + (size_t)(k0 + bk) * NN + n0 + bn);
        __syncthreads();
        #pragma unroll
        for (int k = 0; k < 32; k++) {
            float4 a = *(const float4*)&As[k][tm << 2];
            float2 b = *(const float2*)&Bs[k][tn << 1];
            acc[0][0] += a.x * b.x; acc[0][1] += a.x * b.y;
            acc[1][0] += a.y * b.x; acc[1][1] += a.y * b.y;
            acc[2][0] += a.z * b.x; acc[2][1] += a.z * b.y;
            acc[3][0] += a.w * b.x; acc[3][1] += a.w * b.y;
        }
        __syncthreads();
    }
    int mbase = m0 + (tm << 2), nbase = n0 + (tn << 1);
    #pragma unroll
    for (int i = 0; i < 4; i++)
        #pragma unroll
        for (int j = 0; j < 2; j++)
            Cm[(size_t)(mbase + i) * NN + nbase + j] = acc[i][j];
}

// combine partials + MODE epilogue. 64 blocks x 256 thr x 4 float4 (MLP 8).
// MODE 0: C = S;  1: C = 2E - S;  2: C = I - S;  3: C = E + sfix*S
template<int MODE>
__global__ void combine(const float* __restrict__ P0, const float* __restrict__ P1,
                        const float* __restrict__ Em, float* __restrict__ Cm) {
    int base = blockIdx.x * 256 + threadIdx.x;   // 16384 threads
    #pragma unroll
    for (int j = 0; j < 4; j++) {
        size_t e = ((size_t)(base + j * 16384)) << 2;
        float4 a = *(const float4*)(P0 + e);
        float4 b = *(const float4*)(P1 + e);
        float4 s = make_float4(a.x + b.x, a.y + b.y, a.z + b.z, a.w + b.w);
        float4 c;
        if (MODE == 0) {
            c = s;
        } else if (MODE == 1) {
            float4 ev = *(const float4*)(Em + e);
            c = make_float4(2.f * ev.x - s.x, 2.f * ev.y - s.y, 2.f * ev.z - s.z, 2.f * ev.w - s.w);
        } else if (MODE == 2) {
            int m = (int)(e >> 9), n = (int)(e & 511);
            c.x = (m == n     ? 1.f : 0.f) - s.x;
            c.y = (m == n + 1 ? 1.f : 0.f) - s.y;
            c.z = (m == n + 2 ? 1.f : 0.f) - s.z;
            c.w = (m == n + 3 ? 1.f : 0.f) - s.w;
        } else {
            float sf = g_sfix[0];
            float4 ev = *(const float4*)(Em + e);
            c = make_float4(ev.x + sf * s.x, ev.y + sf * s.y, ev.z + sf * s.z, ev.w + sf * s.w);
        }
        *(float4*)(Cm + e) = c;
    }
}

__global__ void split_kernel(const float* __restrict__ M) {
    int i = blockIdx.x, j = threadIdx.x;
    size_t idx = (size_t)i * NN + j;
    float v = M[idx];
    __nv_bfloat16 h = __float2bfloat16_rn(v);
    g_Mhi[idx] = h;
    g_Mlo[idx] = __float2bfloat16_rn(v - __bfloat162float(h));
}

// ---------------- persistent warp-mma step kernel (916-run version, verbatim) --
// Block r: mi = r>>4 (64-row M tile), ci = r&15 -> b = ci>>1, f0 = (ci&1)*32.
// Dependency group = ci (16 groups of 8 blocks); y tile [64x32] lives in mma
// accumulators across all 128 steps.
// smem: Mhi(64x512) | Mlo | Zhi(32x512) | Zlo, rows padded to 1040B.
#define ASTRIDE  1040
#define MHI_OFF  0
#define MLO_OFF  66560
#define ZHI_OFF  133120
#define ZLO_OFF  166400
#define SM_TOTAL 199680

__global__ void __launch_bounds__(256, 1) step_persist(const float* __restrict__ xs,
                                                       float* __restrict__ out) {
    extern __shared__ char smem[];
    uint32_t sb = smem_u32(smem);
    int tid = threadIdx.x, lane = tid & 31, w = tid >> 5;
    int bx = blockIdx.x;
    int m0 = (bx >> 4) << 6;            // 0..448
    int ci = bx & 15;                   // dependency group id
    int b  = ci >> 1;
    int f0 = (ci & 1) << 5;             // 0 or 32
    unsigned* cnt = &g_gcount[ci][0];
    unsigned* gen = &g_ggen[ci][0];

    int wm = (w & 3) << 4;              // warp m offset within 64
    int wn = (w >> 2) << 4;             // warp f offset within 32

    // ldmatrix lane addresses
    uint32_t aAddr = sb + MHI_OFF + (uint32_t)(wm + (lane & 15)) * ASTRIDE + (((lane >> 4) << 3) << 1);
    uint32_t bAddr = sb + ZHI_OFF + (uint32_t)(wn + ((lane >> 4) << 3) + (lane & 7)) * ASTRIDE
                     + ((((lane >> 3) & 1) << 3) << 1);

    // --- prologue: load M slice into smem (once) ---
    {
        const char* mh = (const char*)(g_Mhi + (size_t)m0 * NN);
        const char* ml = (const char*)(g_Mlo + (size_t)m0 * NN);
        for (int i = tid; i < 64 * 64; i += 256) {
            int r = i >> 6, c = (i & 63) << 4;
            *(uint4*)(smem + MHI_OFF + r * ASTRIDE + c) = *(const uint4*)(mh + r * 1024 + c);
            *(uint4*)(smem + MLO_OFF + r * ASTRIDE + c) = *(const uint4*)(ml + r * 1024 + c);
        }
    }
    // --- prologue: Z0 = x_0 over owned tile -> scratch parity 0 ---
    for (int idx = tid; idx < 64 * 32; idx += 256) {
        int m = idx >> 5, f = idx & 31;
        int gm = m0 + m, gf = f0 + f;
        float v = xs[((size_t)(b * TT) * NN + gm) * FF + gf];
        __nv_bfloat16 h, l; split1(v, h, l);
        g_zhi[0][b][gf][gm] = h;
        g_zlo[0][b][gf][gm] = l;
    }
    group_sync(ci);

    float yacc[2][4] = {};   // y fragments (m16 x n16 per warp), persist across steps

    int r0 = lane >> 2, cc = (lane & 3) << 1;
    int mA = m0 + wm + r0;
    int fj0 = f0 + wn + cc;              // j=0 feature index; j=1 is fj0+8

    for (int t = 0; t < TT; t++) {
        int par = t & 1;
        const char* zh = (const char*)&g_zhi[par][b][f0][0];
        const char* zl = (const char*)&g_zlo[par][b][f0][0];

        // --- prefetch x_{t+1} (consumed in epilogue; latency hidden under mma) ---
        float2 xp00, xp01, xp10, xp11;
        bool notlast = (t < TT - 1);
        if (notlast) {
            const float* xp = xs + ((size_t)(b * TT + t + 1) * NN) * FF;
            xp00 = *(const float2*)(xp + (size_t)mA * FF + fj0);
            xp01 = *(const float2*)(xp + (size_t)(mA + 8) * FF + fj0);
            xp10 = *(const float2*)(xp + (size_t)mA * FF + fj0 + 8);
            xp11 = *(const float2*)(xp + (size_t)(mA + 8) * FF + fj0 + 8);
        }

        // --- issue Z_t in 4 k-quarters (cp.async, L1-bypassed) ---
        #pragma unroll
        for (int q = 0; q < 4; q++) {
            #pragma unroll
            for (int i = 0; i < 4; i++) {
                int idx = tid + (i << 8);
                int op = idx >> 9;
                int rem = idx & 511;
                int r = rem >> 4, c = rem & 15;
                uint32_t off = (uint32_t)r * ASTRIDE + (q << 8) + (c << 4);
                uint32_t goff = (uint32_t)r * 1024 + (q << 8) + (c << 4);
                if (op == 0) cp_async16(sb + ZHI_OFF + off, zh + goff);
                else         cp_async16(sb + ZLO_OFF + off, zl + goff);
            }
            cp_commit();
        }

        // --- mma per quarter, overlapped with remaining quarters' loads ---
        #pragma unroll
        for (int q = 0; q < 4; q++) {
            cp_wait(3 - q);
            __syncthreads();
            #pragma unroll 4
            for (int kk = 0; kk < 128; kk += 16) {
                int k0 = (q << 7) + kk;
                uint32_t ah[4], al[4], bh[4], bl[4];
                uint32_t ka = aAddr + (k0 << 1), kb = bAddr + (k0 << 1);
                ldsm4(ah, ka);
                ldsm4(al, ka + (MLO_OFF - MHI_OFF));
                ldsm4(bh, kb);
                ldsm4(bl, kb + (ZLO_OFF - ZHI_OFF));
                mma_bf16(yacc[0], ah, bh[0], bh[1]);
                mma_bf16(yacc[1], ah, bh[2], bh[3]);
                mma_bf16(yacc[0], ah, bl[0], bl[1]);
                mma_bf16(yacc[1], ah, bl[2], bl[3]);
                mma_bf16(yacc[0], al, bh[0], bh[1]);
                mma_bf16(yacc[1], al, bh[2], bh[3]);
            }
        }

        // --- epilogue: Z_{t+1} first (peers need it), then barrier-arrive,
        //     then out stores (nobody reads out: overlap with peers' wait) ---
        if (notlast) {
            int pn = (t + 1) & 1;
            __nv_bfloat16* zhn = &g_zhi[pn][b][0][0];
            __nv_bfloat16* zln = &g_zlo[pn][b][0][0];
            __nv_bfloat16 h, l;
            split1(xp00.x - yacc[0][0], h, l); zhn[(size_t)fj0 * NN + mA] = h;           zln[(size_t)fj0 * NN + mA] = l;
            split1(xp00.y - yacc[0][1], h, l); zhn[(size_t)(fj0 + 1) * NN + mA] = h;     zln[(size_t)(fj0 + 1) * NN + mA] = l;
            split1(xp01.x - yacc[0][2], h, l); zhn[(size_t)fj0 * NN + mA + 8] = h;       zln[(size_t)fj0 * NN + mA + 8] = l;
            split1(xp01.y - yacc[0][3], h, l); zhn[(size_t)(fj0 + 1) * NN + mA + 8] = h; zln[(size_t)(fj0 + 1) * NN + mA + 8] = l;
            split1(xp10.x - yacc[1][0], h, l); zhn[(size_t)(fj0 + 8) * NN + mA] = h;     zln[(size_t)(fj0 + 8) * NN + mA] = l;
            split1(xp10.y - yacc[1][1], h, l); zhn[(size_t)(fj0 + 9) * NN + mA] = h;     zln[(size_t)(fj0 + 9) * NN + mA] = l;
            split1(xp11.x - yacc[1][2], h, l); zhn[(size_t)(fj0 + 8) * NN + mA + 8] = h; zln[(size_t)(fj0 + 8) * NN + mA + 8] = l;
            split1(xp11.y - yacc[1][3], h, l); zhn[(size_t)(fj0 + 9) * NN + mA + 8] = h; zln[(size_t)(fj0 + 9) * NN + mA + 8] = l;
        }
        __syncthreads();                  // all Z stores issued

        unsigned phase = 0; int amlast = 0;
        if (tid == 0 && notlast) {
            phase = ld_acq(gen);
            __threadfence();              // order CTA's Z stores before arrival
            unsigned prev = atomicAdd(cnt, 1);
            if (prev == GRPSZ - 1) {
                amlast = 1;
                atomicExch(cnt, 0);
                __threadfence();
                atomicAdd(gen, 1);
            }
        }

        // out stores overlap the barrier propagation
        {
            float* op = out + ((size_t)(b * TT + t) * NN) * FF;
            *(float2*)(op + (size_t)mA * FF + fj0)           = make_float2(yacc[0][0], yacc[0][1]);
            *(float2*)(op + (size_t)(mA + 8) * FF + fj0)     = make_float2(yacc[0][2], yacc[0][3]);
            *(float2*)(op + (size_t)mA * FF + fj0 + 8)       = make_float2(yacc[1][0], yacc[1][1]);
            *(float2*)(op + (size_t)(mA + 8) * FF + fj0 + 8) = make_float2(yacc[1][2], yacc[1][3]);
        }

        if (tid == 0 && notlast && !amlast) {
            while (ld_acq(gen) == phase) { }
        }
        __syncthreads();
    }
}

// ---------------- host launcher ----------------
extern "C" void kernel_launch(void* const* d_in, const int* in_sizes, int n_in,
                              void* d_out, int out_size) {
    const float* xs = (const float*)d_in[0];  // [B,T,N,F]
    const float* A  = (const float*)d_in[1];  // [1,N,N]
    float* out = (float*)d_out;               // [B,T,N,F]

    float *pLpI, *pX, *pX2, *pR, *pP0, *pP1;
    cudaGetSymbolAddress((void**)&pLpI, g_LpI);
    cudaGetSymbolAddress((void**)&pX,   g_X);
    cudaGetSymbolAddress((void**)&pX2,  g_X2);
    cudaGetSymbolAddress((void**)&pR,   g_R);
    cudaGetSymbolAddress((void**)&pP0,  g_P0);
    cudaGetSymbolAddress((void**)&pP1,  g_P1);

    cudaFuncSetAttribute(step_persist, cudaFuncAttributeMaxDynamicSharedMemorySize, SM_TOTAL);

    // 1) build (L+I); X1 computed analytically (replaces first NS GEMM pair)
    rowsum_kernel<<<NN, 128>>>(A);
    build_kernel<<<NN, 512>>>(A);
    build_x1_kernel<<<NN, 512>>>();

    dim3 gridp(NN / 32, NN / 64, 2);   // k-split x2 -> 256 blocks
    dim3 gridc(64);

    // 2) Newton-Schulz iterations 2..4 (NS4 total; NS3 failed at 1.1e-3 in R7)
    float* Xin = pX; float* Xout = pX2;
    for (int it = 0; it < 3; it++) {
        gemm_part<<<gridp, 256>>>(pLpI, Xin, pP0, pP1);
        combine<0><<<gridc, 256>>>(pP0, pP1, nullptr, pR);      // R = (L+I)@X
        gemm_part<<<gridp, 256>>>(Xin, pR, pP0, pP1);
        combine<1><<<gridc, 256>>>(pP0, pP1, Xin, Xout);        // Xout = 2X - X@R
        float* tmp = Xin; Xin = Xout; Xout = tmp;
    }

    // 3) rank-1 closed-form fix: R = I - X@(L+I); M = X + R@X / (1 - tr R)
    gemm_part<<<gridp, 256>>>(Xin, pLpI, pP0, pP1);
    combine<2><<<gridc, 256>>>(pP0, pP1, nullptr, pR);
    trace_kernel<<<1, 256>>>();
    gemm_part<<<gridp, 256>>>(pR, Xin, pP0, pP1);
    combine<3><<<gridc, 256>>>(pP0, pP1, Xin, Xout);

    // 4) split M into bf16 hi/lo
    split_kernel<<<NN, 512>>>(Xout);

    // 5) all 128 recurrence steps in ONE persistent tensor-core kernel
    step_persist<<<NBLK, 256, SM_TOTAL>>>(xs, out);
}